// round 8
// baseline (speedup 1.0000x reference)
#include <cuda_runtime.h>

#define N_NODES   50000
#define N_EDGES   800000
#define D         96
#define OUT_COLS  384            // 4 * D (concat of x,h1,h2,h3)
#define M_TILE    64             // rows per MLP block
#define IN_LD     97             // padded smem row stride (bank-conflict break)

// NO __device__ scratch: aggregation buffers live inside d_out.
// S_l = out[:, l*96 : (l+1)*96], row stride OUT_COLS.

// ---------------------------------------------------------------------------
// init: S0 = x ; S1 = x   (float4 throughout; all pointers 16B-aligned)
// ---------------------------------------------------------------------------
__global__ void init_kernel(const float* __restrict__ x, float* __restrict__ out) {
    int gid = blockIdx.x * blockDim.x + threadIdx.x;   // over N_NODES*24 float4
    if (gid >= N_NODES * (D / 4)) return;
    int node = gid / (D / 4);
    int c    = gid % (D / 4);
    float4 v = reinterpret_cast<const float4*>(x)[gid];
    float4* row = reinterpret_cast<float4*>(out + (size_t)node * OUT_COLS);
    row[c]            = v;   // S0
    row[(D / 4) + c]  = v;   // S1 (aggr init for layer 0: aggr = h)
}

// ---------------------------------------------------------------------------
// scatter: S_next[dst] += S_cur[src]
// edge_index arrives as int32 (harness narrows int64 -> int32).
// 384 threads = 4 edges x 96 columns; exactly ONE scalar atomicAdd per thread.
// ---------------------------------------------------------------------------
__global__ void scatter_kernel(const float* __restrict__ cur,
                               float* __restrict__ next,
                               const int* __restrict__ ei) {
    int tid = threadIdx.x;                    // 0..383
    int e   = blockIdx.x * 4 + tid / 96;
    int c   = tid % 96;
    int src = ei[e];
    int dst = ei[N_EDGES + e];
    float v = cur[(size_t)src * OUT_COLS + c];
    atomicAdd(next + (size_t)dst * OUT_COLS + c, v);
}

// ---------------------------------------------------------------------------
// mlp: slice := relu(slice @ w1 + b1) @ w2 + b2   (in place, per-block safe)
// Optionally mirrors the result into nxt (aggr init for the next layer).
// Block = 64 rows, 256 threads as (tx=16, ty=16); micro-tile 4 rows x 6 cols.
// Smem: w (96x96) + in (64x97) + tmp (64x97) = 86528 B dynamic.
// ---------------------------------------------------------------------------
__global__ void mlp_kernel(const float* __restrict__ w1, const float* __restrict__ b1,
                           const float* __restrict__ w2, const float* __restrict__ b2,
                           float* __restrict__ slice, float* __restrict__ nxt) {
    extern __shared__ float smem[];
    float* sW   = smem;                    // 96*96
    float* sIn  = sW  + D * D;             // 64*97
    float* sTmp = sIn + M_TILE * IN_LD;    // 64*97

    const int tid = threadIdx.x;
    const int tx  = tid & 15;              // 0..15 -> 6 output cols each
    const int ty  = tid >> 4;              // 0..15 -> 4 output rows each
    const int rowBase = blockIdx.x * M_TILE;

    // load w1 (coalesced float4)
    for (int i = tid; i < D * D / 4; i += 256)
        reinterpret_cast<float4*>(sW)[i] = reinterpret_cast<const float4*>(w1)[i];
    // load this block's 64-row input tile from the slice (stride OUT_COLS)
    for (int i = tid; i < M_TILE * (D / 4); i += 256) {
        int r  = i / (D / 4);
        int cc = i % (D / 4);
        int row = rowBase + r;
        float4 v = make_float4(0.f, 0.f, 0.f, 0.f);
        if (row < N_NODES)
            v = *reinterpret_cast<const float4*>(slice + (size_t)row * OUT_COLS + cc * 4);
        float* dp = sIn + r * IN_LD + cc * 4;
        dp[0] = v.x; dp[1] = v.y; dp[2] = v.z; dp[3] = v.w;
    }
    __syncthreads();

    // ---- phase 1: tmp = relu(in @ w1 + b1) ----
    float acc[4][6];
    #pragma unroll
    for (int r = 0; r < 4; ++r)
        #pragma unroll
        for (int j = 0; j < 6; ++j) acc[r][j] = 0.f;

    #pragma unroll 8
    for (int k = 0; k < D; ++k) {
        float a[4], b[6];
        #pragma unroll
        for (int r = 0; r < 4; ++r) a[r] = sIn[(ty * 4 + r) * IN_LD + k];
        #pragma unroll
        for (int j = 0; j < 6; ++j) b[j] = sW[k * D + tx * 6 + j];
        #pragma unroll
        for (int r = 0; r < 4; ++r)
            #pragma unroll
            for (int j = 0; j < 6; ++j) acc[r][j] = fmaf(a[r], b[j], acc[r][j]);
    }
    #pragma unroll
    for (int r = 0; r < 4; ++r)
        #pragma unroll
        for (int j = 0; j < 6; ++j) {
            float v = acc[r][j] + b1[tx * 6 + j];
            sTmp[(ty * 4 + r) * IN_LD + tx * 6 + j] = fmaxf(v, 0.f);
        }
    __syncthreads();

    // swap in w2
    for (int i = tid; i < D * D / 4; i += 256)
        reinterpret_cast<float4*>(sW)[i] = reinterpret_cast<const float4*>(w2)[i];
    __syncthreads();

    // ---- phase 2: out = tmp @ w2 + b2 ----
    #pragma unroll
    for (int r = 0; r < 4; ++r)
        #pragma unroll
        for (int j = 0; j < 6; ++j) acc[r][j] = 0.f;

    #pragma unroll 8
    for (int k = 0; k < D; ++k) {
        float a[4], b[6];
        #pragma unroll
        for (int r = 0; r < 4; ++r) a[r] = sTmp[(ty * 4 + r) * IN_LD + k];
        #pragma unroll
        for (int j = 0; j < 6; ++j) b[j] = sW[k * D + tx * 6 + j];
        #pragma unroll
        for (int r = 0; r < 4; ++r)
            #pragma unroll
            for (int j = 0; j < 6; ++j) acc[r][j] = fmaf(a[r], b[j], acc[r][j]);
    }

    #pragma unroll
    for (int r = 0; r < 4; ++r) {
        int row = rowBase + ty * 4 + r;
        if (row >= N_NODES) continue;
        #pragma unroll
        for (int j = 0; j < 6; ++j) {
            int col = tx * 6 + j;
            float v = acc[r][j] + b2[col];
            slice[(size_t)row * OUT_COLS + col] = v;          // final h for this layer
            if (nxt) nxt[(size_t)row * OUT_COLS + col] = v;   // aggr init for next layer
        }
    }
}

// ---------------------------------------------------------------------------
extern "C" void kernel_launch(void* const* d_in, const int* in_sizes, int n_in,
                              void* d_out, int out_size) {
    const float* x  = (const float*)d_in[0];
    const int*   ei = (const int*)d_in[1];
    const float* W[12];
    for (int i = 0; i < 12; ++i) W[i] = (const float*)d_in[2 + i];
    float* out = (float*)d_out;

    const int SMEM_BYTES = (D * D + 2 * M_TILE * IN_LD) * (int)sizeof(float); // 86528
    cudaFuncSetAttribute(mlp_kernel, cudaFuncAttributeMaxDynamicSharedMemorySize, SMEM_BYTES);

    init_kernel<<<(N_NODES * (D / 4) + 255) / 256, 256>>>(x, out);

    for (int l = 0; l < 3; ++l) {
        float* cur = out + (size_t)l * D;        // S_l     (finalized h_l)
        float* agg = out + (size_t)(l + 1) * D;  // S_{l+1} (holds h_l copy, becomes aggr)
        float* nxt = (l < 2) ? out + (size_t)(l + 2) * D : nullptr;

        scatter_kernel<<<N_EDGES / 4, 384>>>(cur, agg, ei);
        mlp_kernel<<<(N_NODES + M_TILE - 1) / M_TILE, 256, SMEM_BYTES>>>(
            W[4 * l + 0], W[4 * l + 1], W[4 * l + 2], W[4 * l + 3], agg, nxt);
    }
}

// round 9
// speedup vs baseline: 1.9816x; 1.9816x over previous
#include <cuda_runtime.h>

#define N_NODES   50000
#define N_EDGES   800000
#define D         96
#define OUT_COLS  384            // 4 * D (concat of x,h1,h2,h3)
#define M_TILE    64             // rows per MLP block
#define IN_LD     97             // padded smem row stride (bank-conflict break)

// NO __device__ scratch: aggregation buffers live inside d_out.
// S_l = out[:, l*96 : (l+1)*96], row stride OUT_COLS.

// ---------------------------------------------------------------------------
// init: S0 = x ; S1 = x   (float4 throughout; all pointers 16B-aligned)
// ---------------------------------------------------------------------------
__global__ void init_kernel(const float* __restrict__ x, float* __restrict__ out) {
    int gid = blockIdx.x * blockDim.x + threadIdx.x;   // over N_NODES*24 float4
    if (gid >= N_NODES * (D / 4)) return;
    int node = gid / (D / 4);
    int c    = gid % (D / 4);
    float4 v = reinterpret_cast<const float4*>(x)[gid];
    float4* row = reinterpret_cast<float4*>(out + (size_t)node * OUT_COLS);
    row[c]            = v;   // S0
    row[(D / 4) + c]  = v;   // S1 (aggr init for layer 0: aggr = h)
}

// ---------------------------------------------------------------------------
// scatter: S_next[dst] += S_cur[src]
// 192 threads = 8 edge-lanes x 24 float4-chunks; each thread handles 4 edges
// (batched: all index loads, then all value loads, then all vector REDs)
// -> MLP ~4-8 instead of 1. float4 atomicAdd = RED.E.ADD.F32x4 (sm_90+).
// Block covers 32 edges; grid = 25000.
// ---------------------------------------------------------------------------
#define EDGES_PER_BLOCK 32
__global__ void scatter_kernel(const float* __restrict__ cur,
                               float* __restrict__ next,
                               const int* __restrict__ ei) {
    const int tid = threadIdx.x;          // 0..191
    const int c   = tid % 24;             // float4 chunk within row
    const int s   = tid / 24;             // 0..7 edge lane
    const int base = blockIdx.x * EDGES_PER_BLOCK + s;

    int srcs[4], dsts[4];
    #pragma unroll
    for (int it = 0; it < 4; ++it) {
        int e = base + it * 8;
        srcs[it] = __ldg(&ei[e]);
        dsts[it] = __ldg(&ei[N_EDGES + e]);
    }
    float4 vs[4];
    #pragma unroll
    for (int it = 0; it < 4; ++it)
        vs[it] = *reinterpret_cast<const float4*>(cur + (size_t)srcs[it] * OUT_COLS + c * 4);
    #pragma unroll
    for (int it = 0; it < 4; ++it)
        atomicAdd(reinterpret_cast<float4*>(next + (size_t)dsts[it] * OUT_COLS + c * 4), vs[it]);
}

// ---------------------------------------------------------------------------
// mlp: slice := relu(slice @ w1 + b1) @ w2 + b2   (in place, per-block safe)
// Optionally mirrors the result into nxt (aggr init for the next layer).
// Block = 64 rows, 256 threads as (tx=16, ty=16); micro-tile 4 rows x 6 cols.
// Smem: w (96x96) + in (64x97) + tmp (64x97) = 86528 B dynamic.
// ---------------------------------------------------------------------------
__global__ void mlp_kernel(const float* __restrict__ w1, const float* __restrict__ b1,
                           const float* __restrict__ w2, const float* __restrict__ b2,
                           float* __restrict__ slice, float* __restrict__ nxt) {
    extern __shared__ float smem[];
    float* sW   = smem;                    // 96*96
    float* sIn  = sW  + D * D;             // 64*97
    float* sTmp = sIn + M_TILE * IN_LD;    // 64*97

    const int tid = threadIdx.x;
    const int tx  = tid & 15;              // 0..15 -> 6 output cols each
    const int ty  = tid >> 4;              // 0..15 -> 4 output rows each
    const int rowBase = blockIdx.x * M_TILE;

    // load w1 (coalesced float4)
    for (int i = tid; i < D * D / 4; i += 256)
        reinterpret_cast<float4*>(sW)[i] = reinterpret_cast<const float4*>(w1)[i];
    // load this block's 64-row input tile from the slice (stride OUT_COLS)
    for (int i = tid; i < M_TILE * (D / 4); i += 256) {
        int r  = i / (D / 4);
        int cc = i % (D / 4);
        int row = rowBase + r;
        float4 v = make_float4(0.f, 0.f, 0.f, 0.f);
        if (row < N_NODES)
            v = *reinterpret_cast<const float4*>(slice + (size_t)row * OUT_COLS + cc * 4);
        float* dp = sIn + r * IN_LD + cc * 4;
        dp[0] = v.x; dp[1] = v.y; dp[2] = v.z; dp[3] = v.w;
    }
    __syncthreads();

    // ---- phase 1: tmp = relu(in @ w1 + b1) ----
    float acc[4][6];
    #pragma unroll
    for (int r = 0; r < 4; ++r)
        #pragma unroll
        for (int j = 0; j < 6; ++j) acc[r][j] = 0.f;

    #pragma unroll 8
    for (int k = 0; k < D; ++k) {
        float a[4], b[6];
        #pragma unroll
        for (int r = 0; r < 4; ++r) a[r] = sIn[(ty * 4 + r) * IN_LD + k];
        #pragma unroll
        for (int j = 0; j < 6; ++j) b[j] = sW[k * D + tx * 6 + j];
        #pragma unroll
        for (int r = 0; r < 4; ++r)
            #pragma unroll
            for (int j = 0; j < 6; ++j) acc[r][j] = fmaf(a[r], b[j], acc[r][j]);
    }
    #pragma unroll
    for (int r = 0; r < 4; ++r)
        #pragma unroll
        for (int j = 0; j < 6; ++j) {
            float v = acc[r][j] + b1[tx * 6 + j];
            sTmp[(ty * 4 + r) * IN_LD + tx * 6 + j] = fmaxf(v, 0.f);
        }
    __syncthreads();

    // swap in w2
    for (int i = tid; i < D * D / 4; i += 256)
        reinterpret_cast<float4*>(sW)[i] = reinterpret_cast<const float4*>(w2)[i];
    __syncthreads();

    // ---- phase 2: out = tmp @ w2 + b2 ----
    #pragma unroll
    for (int r = 0; r < 4; ++r)
        #pragma unroll
        for (int j = 0; j < 6; ++j) acc[r][j] = 0.f;

    #pragma unroll 8
    for (int k = 0; k < D; ++k) {
        float a[4], b[6];
        #pragma unroll
        for (int r = 0; r < 4; ++r) a[r] = sTmp[(ty * 4 + r) * IN_LD + k];
        #pragma unroll
        for (int j = 0; j < 6; ++j) b[j] = sW[k * D + tx * 6 + j];
        #pragma unroll
        for (int r = 0; r < 4; ++r)
            #pragma unroll
            for (int j = 0; j < 6; ++j) acc[r][j] = fmaf(a[r], b[j], acc[r][j]);
    }

    #pragma unroll
    for (int r = 0; r < 4; ++r) {
        int row = rowBase + ty * 4 + r;
        if (row >= N_NODES) continue;
        #pragma unroll
        for (int j = 0; j < 6; ++j) {
            int col = tx * 6 + j;
            float v = acc[r][j] + b2[col];
            slice[(size_t)row * OUT_COLS + col] = v;          // final h for this layer
            if (nxt) nxt[(size_t)row * OUT_COLS + col] = v;   // aggr init for next layer
        }
    }
}

// ---------------------------------------------------------------------------
extern "C" void kernel_launch(void* const* d_in, const int* in_sizes, int n_in,
                              void* d_out, int out_size) {
    const float* x  = (const float*)d_in[0];
    const int*   ei = (const int*)d_in[1];
    const float* W[12];
    for (int i = 0; i < 12; ++i) W[i] = (const float*)d_in[2 + i];
    float* out = (float*)d_out;

    const int SMEM_BYTES = (D * D + 2 * M_TILE * IN_LD) * (int)sizeof(float); // 86528
    cudaFuncSetAttribute(mlp_kernel, cudaFuncAttributeMaxDynamicSharedMemorySize, SMEM_BYTES);

    init_kernel<<<(N_NODES * (D / 4) + 255) / 256, 256>>>(x, out);

    for (int l = 0; l < 3; ++l) {
        float* cur = out + (size_t)l * D;        // S_l     (finalized h_l)
        float* agg = out + (size_t)(l + 1) * D;  // S_{l+1} (holds h_l copy, becomes aggr)
        float* nxt = (l < 2) ? out + (size_t)(l + 2) * D : nullptr;

        scatter_kernel<<<N_EDGES / EDGES_PER_BLOCK, 192>>>(cur, agg, ei);
        mlp_kernel<<<(N_NODES + M_TILE - 1) / M_TILE, 256, SMEM_BYTES>>>(
            W[4 * l + 0], W[4 * l + 1], W[4 * l + 2], W[4 * l + 3], agg, nxt);
    }
}